// round 5
// baseline (speedup 1.0000x reference)
#include <cuda_runtime.h>

// tiles: (154, 7, 28, 16, 16, 16) fp32
// occupancy: (8,8,8) bool (encoding auto-detected)
// output: (7, 1, 28, 64, 64, 64) fp32 == (196, 64, 64, 64), window offset 8, 5x5x5 tiles
#define NT 5
#define OFF 8
#define JC 196
#define JC_GRP 49            // jc = grp + 49*k, k=0..3
#define TILE_STRIDE 4096     // 16^3 floats per (tile,jc) slab
#define OUT_JC_F4 65536      // 64*64*64/4 float4 per jc
// each thread: 2 z-float4 (one 32B pair) x 4 jc  -> 8 loads / 8 stores
#define N_THREADS (JC_GRP * 64 * 64 * 8)   // 1,605,632

__device__ int g_lut[NT * NT * NT];

// Fast LUT: warp ballots -> 16-word bitmap -> popcount prefix. ~3 syncs.
__global__ void build_lut_kernel(const unsigned char* __restrict__ occ_raw) {
    __shared__ unsigned int words[16];
    __shared__ int wsum[16];
    __shared__ int enc_bytes;
    const int t = threadIdx.x;          // 0..511
    const int warp = t >> 5, lane = t & 31;

    const int b = occ_raw[t];
    // warp byte-sum for encoding detection
    int s = b;
    #pragma unroll
    for (int o = 16; o > 0; o >>= 1) s += __shfl_down_sync(0xffffffffu, s, o);
    if (lane == 0) wsum[warp] = s;
    __syncthreads();
    if (t == 0) {
        int tot = 0;
        #pragma unroll
        for (int i = 0; i < 16; i++) tot += wsum[i];
        // byte-bool: sum == 154 (>128). widened 32-bit: first 512 bytes cover
        // 128 cells -> byte sum <= 128.
        enc_bytes = (tot > 128) ? 1 : 0;
    }
    __syncthreads();

    int v;
    if (enc_bytes) v = (b != 0);
    else           v = (reinterpret_cast<const unsigned int*>(occ_raw)[t] != 0u);

    const unsigned int bal = __ballot_sync(0xffffffffu, v);
    if (lane == 0) words[warp] = bal;
    __syncthreads();

    // exclusive prefix popcount = tile index
    int idx = __popc(words[warp] & ((1u << lane) - 1u));
    for (int i = 0; i < warp; i++) idx += __popc(words[i]);

    const int tx = t >> 6;
    const int ty = (t >> 3) & 7;
    const int tz = t & 7;
    if (tx < NT && ty < NT && tz < NT)
        g_lut[(tx * NT + ty) * NT + tz] = v ? idx : -1;
}

// Each thread: spatial z-pair (two adjacent float4s, same source tile,
// contiguous 32B in the slab) x 4 jc channels. 8 independent LDG.128 (MLP=8),
// 8 streaming STG.128.
__global__ void __launch_bounds__(256) gather_kernel(
    const float* __restrict__ tiles, float4* __restrict__ out) {
    const int id = blockIdx.x * 256 + threadIdx.x;   // < 1,605,632

    const int zp = id & 7;               // z = 8*zp .. 8*zp+7
    int tmp = id >> 3;
    const int y = tmp & 63;  tmp >>= 6;
    const int x = tmp & 63;  tmp >>= 6;
    const int grp = tmp;                 // 0..48

    const int gz = (zp << 3) + OFF;      // pair (gz, gz+4) always same tile
    const int gy = y + OFF;
    const int gx = x + OFF;
    const int tz = gz >> 4, iz = gz & 15;
    const int ty = gy >> 4, iy = gy & 15;
    const int tx = gx >> 4, ix = gx & 15;

    const int tidx = g_lut[(tx * NT + ty) * NT + tz];
    const int spatial_src = (ix << 8) + (iy << 4) + iz;   // float offset in slab
    const int spatial_out = (x << 10) + (y << 4) + (zp << 1); // float4 offset in jc

    float4 a0 = make_float4(0.f, 0.f, 0.f, 0.f), b0 = a0;
    float4 a1 = a0, b1 = a0, a2 = a0, b2 = a0, a3 = a0, b3 = a0;

    if (tidx >= 0) {
        const float4* base = reinterpret_cast<const float4*>(
            tiles + (size_t)(tidx * JC + grp) * TILE_STRIDE + spatial_src);
        const size_t st = (size_t)JC_GRP * TILE_STRIDE / 4;   // float4 stride per k
        a0 = __ldcs(base);              b0 = __ldcs(base + 1);
        a1 = __ldcs(base + st);         b1 = __ldcs(base + st + 1);
        a2 = __ldcs(base + 2 * st);     b2 = __ldcs(base + 2 * st + 1);
        a3 = __ldcs(base + 3 * st);     b3 = __ldcs(base + 3 * st + 1);
    }

    float4* o = out + spatial_out + (size_t)grp * OUT_JC_F4;
    const size_t ot = (size_t)JC_GRP * OUT_JC_F4;
    __stcs(o,          a0); __stcs(o + 1,          b0);
    __stcs(o + ot,     a1); __stcs(o + ot + 1,     b1);
    __stcs(o + 2 * ot, a2); __stcs(o + 2 * ot + 1, b2);
    __stcs(o + 3 * ot, a3); __stcs(o + 3 * ot + 1, b3);
}

extern "C" void kernel_launch(void* const* d_in, const int* in_sizes, int n_in,
                              void* d_out, int out_size) {
    const float* tiles = (const float*)d_in[0];
    const unsigned char* occ = (const unsigned char*)d_in[1];

    build_lut_kernel<<<1, 512>>>(occ);
    gather_kernel<<<N_THREADS / 256, 256>>>(tiles, (float4*)d_out);
}

// round 6
// speedup vs baseline: 1.1498x; 1.1498x over previous
#include <cuda_runtime.h>

// tiles: (154, 7, 28, 16, 16, 16) fp32
// occupancy: (8,8,8) bool (encoding auto-detected)
// output: (7, 1, 28, 64, 64, 64) fp32 == (196, 64, 64, 64), window offset 8, 5x5x5 tiles
#define NT 5
#define OFF 8
#define JC 196
#define NC 28                 // c = 0..27 in thread id; j = 0..6 unrolled (MLP=7)
#define TILE_STRIDE 4096      // 16^3 floats per (tile,jc) slab
#define OUT_JC_F4 65536       // 64*64*64/4 float4 per jc
#define N_THREADS (NC * 64 * 64 * 16)   // 1,835,008 -> 7168 blocks

__device__ int g_lut[NT * NT * NT];

// LUT: warp ballots -> 16-word bitmap -> popcount prefix.
__global__ void build_lut_kernel(const unsigned char* __restrict__ occ_raw) {
    __shared__ unsigned int words[16];
    __shared__ int wsum[16];
    __shared__ int enc_bytes;
    const int t = threadIdx.x;          // 0..511
    const int warp = t >> 5, lane = t & 31;

    const int b = occ_raw[t];
    int s = b;
    #pragma unroll
    for (int o = 16; o > 0; o >>= 1) s += __shfl_down_sync(0xffffffffu, s, o);
    if (lane == 0) wsum[warp] = s;
    __syncthreads();
    if (t == 0) {
        int tot = 0;
        #pragma unroll
        for (int i = 0; i < 16; i++) tot += wsum[i];
        // byte-bool: sum == 154 (>128). widened 32-bit: first 512 bytes cover
        // 128 cells -> byte sum <= 128.
        enc_bytes = (tot > 128) ? 1 : 0;
    }
    __syncthreads();

    int v;
    if (enc_bytes) v = (b != 0);
    else           v = (reinterpret_cast<const unsigned int*>(occ_raw)[t] != 0u);

    const unsigned int bal = __ballot_sync(0xffffffffu, v);
    if (lane == 0) words[warp] = bal;
    __syncthreads();

    int idx = __popc(words[warp] & ((1u << lane) - 1u));
    for (int i = 0; i < warp; i++) idx += __popc(words[i]);

    const int tx = t >> 6;
    const int ty = (t >> 3) & 7;
    const int tz = t & 7;
    if (tx < NT && ty < NT && tz < NT)
        g_lut[(tx * NT + ty) * NT + tz] = v ? idx : -1;
}

// Each thread: one spatial float4 cell (zi in low bits -> dense 512B warp
// stores), 7 j-channels (jc = j*28 + c). One LUT lookup, 7 independent
// LDG.128 (MLP=7), 7 dense streaming STG.128.
__global__ void __launch_bounds__(256) gather_kernel(
    const float* __restrict__ tiles, float4* __restrict__ out) {
    const int id = blockIdx.x * 256 + threadIdx.x;   // < 1,835,008

    const int zi = id & 15;              // z = 4*zi
    int tmp = id >> 4;
    const int y = tmp & 63;  tmp >>= 6;
    const int x = tmp & 63;  tmp >>= 6;
    const int c = tmp;                   // 0..27

    const int gz = (zi << 2) + OFF;
    const int gy = y + OFF;
    const int gx = x + OFF;
    const int tz = gz >> 4, iz = gz & 15;
    const int ty = gy >> 4, iy = gy & 15;
    const int tx = gx >> 4, ix = gx & 15;

    const int tidx = g_lut[(tx * NT + ty) * NT + tz];
    const int spatial_src = (ix << 8) + (iy << 4) + iz;      // float offset in slab
    const int spatial_out = (x << 10) + (y << 4) + zi;       // float4 offset in jc

    float4 v[7];
    #pragma unroll
    for (int j = 0; j < 7; j++) v[j] = make_float4(0.f, 0.f, 0.f, 0.f);

    if (tidx >= 0) {
        const float4* base = reinterpret_cast<const float4*>(
            tiles + (size_t)(tidx * JC + c) * TILE_STRIDE + spatial_src);
        const size_t st = (size_t)NC * TILE_STRIDE / 4;      // float4 stride per j
        #pragma unroll
        for (int j = 0; j < 7; j++) v[j] = __ldcs(base + j * st);
    }

    float4* o = out + spatial_out + (size_t)c * OUT_JC_F4;
    const size_t ot = (size_t)NC * OUT_JC_F4;
    #pragma unroll
    for (int j = 0; j < 7; j++) __stcs(o + j * ot, v[j]);
}

extern "C" void kernel_launch(void* const* d_in, const int* in_sizes, int n_in,
                              void* d_out, int out_size) {
    const float* tiles = (const float*)d_in[0];
    const unsigned char* occ = (const unsigned char*)d_in[1];

    build_lut_kernel<<<1, 512>>>(occ);
    gather_kernel<<<N_THREADS / 256, 256>>>(tiles, (float4*)d_out);
}